// round 3
// baseline (speedup 1.0000x reference)
#include <cuda_runtime.h>
#include <cuda_bf16.h>
#include <cstdint>

// ---------------------------------------------------------------------------
// SimpleGCN: 2-layer GCN on N=100000 nodes, 128->128->64, E=1.6M edges + self
// loops, symmetric normalization, log_softmax output.
//
// Pipeline (all fp32):
//   0. detect edge_index dtype (JAX x64-disabled => int32 despite jnp.int64)
//   1. zero scratch (a1, a2, deg)
//   2. edge_prep: edge_index -> int32 src/dst + in-degree histogram
//   3. dinv[i] = rsqrt(deg[i] + 1)            (+1 = self loop)
//   4. h1 = x @ W1                            (register-tiled SGEMM)
//   5. scatter1: a1[dst] += h1[src]*dinv[s]*dinv[d]   (red.global.add.v4.f32)
//   6. h2 = relu(a1 + h1*dinv^2 + b1) @ W2    (self-loop + bias + relu fused)
//   7. scatter2: a2[dst] += h2[src]*norm
//   8. finalize: v = a2 + h2*dinv^2 + b2 ; out = log_softmax(v)
//
// R1 fix: 16B alignment on all vector-accessed scratch.
// R2 fix: edge_index is int32 under default JAX (x64 disabled); reading it as
//         int64 read 2x past the buffer end -> illegal memory access. Now a
//         device-side detector picks the dtype (odd words all-zero <=> int64).
// ---------------------------------------------------------------------------

#define NMAX 100000
#define EMAX 1600000
#define F_IN 128
#define F_MID 128
#define F_OUT 64

__device__ __align__(16) int   g_src[EMAX];
__device__ __align__(16) int   g_dst[EMAX];
__device__ __align__(16) int   g_deg[NMAX];
__device__ __align__(16) float g_dinv[NMAX];
__device__ __align__(16) float g_h1[(size_t)NMAX * F_MID];
__device__ __align__(16) float g_a1[(size_t)NMAX * F_MID];
__device__ __align__(16) float g_h2[(size_t)NMAX * F_OUT];
__device__ __align__(16) float g_a2[(size_t)NMAX * F_OUT];
__device__ int g_is64;

__device__ __forceinline__ void red_add_v4(float* ptr, float4 v) {
    asm volatile("red.global.add.v4.f32 [%0], {%1, %2, %3, %4};"
                 :: "l"(ptr), "f"(v.x), "f"(v.y), "f"(v.z), "f"(v.w)
                 : "memory");
}

// ---------------------------------------------------------------------------
// 0. dtype detect: if the buffer is int64 node-ids (< 2^31), every odd int32
//    word is 0. For int32 data the odd words are random node ids.
// ---------------------------------------------------------------------------
__global__ void detect_kernel(const int* __restrict__ ei32) {
    if (threadIdx.x == 0 && blockIdx.x == 0) {
        int allzero = 1;
        for (int i = 0; i < 64; i++) {
            if (ei32[2 * i + 1] != 0) { allzero = 0; break; }
        }
        g_is64 = allzero;
    }
}

// ---------------------------------------------------------------------------
// 1. zero a1, a2, deg
// ---------------------------------------------------------------------------
__global__ void zero_kernel() {
    const long long n1 = (long long)NMAX * F_MID / 4;
    const long long n2 = (long long)NMAX * F_OUT / 4;
    const long long total = n1 + n2;
    long long stride = (long long)gridDim.x * blockDim.x;
    float4 z = make_float4(0.f, 0.f, 0.f, 0.f);
    for (long long i = (long long)blockIdx.x * blockDim.x + threadIdx.x;
         i < total; i += stride) {
        if (i < n1) reinterpret_cast<float4*>(g_a1)[i] = z;
        else        reinterpret_cast<float4*>(g_a2)[i - n1] = z;
    }
    for (long long i = (long long)blockIdx.x * blockDim.x + threadIdx.x;
         i < NMAX; i += stride) {
        g_deg[(int)i] = 0;
    }
}

// ---------------------------------------------------------------------------
// 2. edge decode (dtype-agnostic) + degree histogram
// ---------------------------------------------------------------------------
__global__ void edge_prep_kernel(const void* __restrict__ ei_raw, int E, int N) {
    const int is64 = g_is64;
    const int stride = gridDim.x * blockDim.x;
    const int* __restrict__ p32 = (const int*)ei_raw;
    const long long* __restrict__ p64 = (const long long*)ei_raw;
    for (int e = blockIdx.x * blockDim.x + threadIdx.x; e < E; e += stride) {
        int s, d;
        if (is64) {
            s = (int)p64[e];
            d = (int)p64[(size_t)E + e];
        } else {
            s = p32[e];
            d = p32[(size_t)E + e];
        }
        // defensive clamp (should never trigger)
        s = min(max(s, 0), N - 1);
        d = min(max(d, 0), N - 1);
        g_src[e] = s;
        g_dst[e] = d;
        atomicAdd(&g_deg[d], 1);
    }
}

// ---------------------------------------------------------------------------
// 3. dinv
// ---------------------------------------------------------------------------
__global__ void dinv_kernel(int N) {
    int i = blockIdx.x * blockDim.x + threadIdx.x;
    if (i < N) g_dinv[i] = rsqrtf((float)(g_deg[i] + 1));
}

// ---------------------------------------------------------------------------
// 4. GEMM1: g_h1 = x @ W1   (N x 128) @ (128 x 128)
// ---------------------------------------------------------------------------
__global__ void gemm1_kernel(const float* __restrict__ X,
                             const float* __restrict__ W, int N) {
    __shared__ float xs[64][64];
    __shared__ float ws[64][64];
    int tid = threadIdx.x;
    int tx = tid & 15;
    int ty = tid >> 4;
    int row0 = blockIdx.x * 64;
    int col0 = blockIdx.y * 64;

    float acc[4][4];
#pragma unroll
    for (int i = 0; i < 4; i++)
#pragma unroll
        for (int j = 0; j < 4; j++) acc[i][j] = 0.f;

    for (int k0 = 0; k0 < F_IN; k0 += 64) {
#pragma unroll
        for (int i = 0; i < 4; i++) {
            int t = tid + i * 256;
            int r = t >> 4;
            int c4 = t & 15;
            float4 v = make_float4(0.f, 0.f, 0.f, 0.f);
            int gr = row0 + r;
            if (gr < N)
                v = *reinterpret_cast<const float4*>(&X[(size_t)gr * F_IN + k0 + c4 * 4]);
            *reinterpret_cast<float4*>(&xs[r][c4 * 4]) = v;
        }
#pragma unroll
        for (int i = 0; i < 4; i++) {
            int t = tid + i * 256;
            int r = t >> 4;
            int c4 = t & 15;
            float4 v = *reinterpret_cast<const float4*>(&W[(size_t)(k0 + r) * F_MID + col0 + c4 * 4]);
            *reinterpret_cast<float4*>(&ws[r][c4 * 4]) = v;
        }
        __syncthreads();
#pragma unroll 16
        for (int k = 0; k < 64; k++) {
            float4 w = *reinterpret_cast<float4*>(&ws[k][tx * 4]);
            float x0 = xs[ty * 4 + 0][k];
            float x1 = xs[ty * 4 + 1][k];
            float x2 = xs[ty * 4 + 2][k];
            float x3 = xs[ty * 4 + 3][k];
            acc[0][0] += x0 * w.x; acc[0][1] += x0 * w.y; acc[0][2] += x0 * w.z; acc[0][3] += x0 * w.w;
            acc[1][0] += x1 * w.x; acc[1][1] += x1 * w.y; acc[1][2] += x1 * w.z; acc[1][3] += x1 * w.w;
            acc[2][0] += x2 * w.x; acc[2][1] += x2 * w.y; acc[2][2] += x2 * w.z; acc[2][3] += x2 * w.w;
            acc[3][0] += x3 * w.x; acc[3][1] += x3 * w.y; acc[3][2] += x3 * w.z; acc[3][3] += x3 * w.w;
        }
        __syncthreads();
    }
#pragma unroll
    for (int i = 0; i < 4; i++) {
        int gr = row0 + ty * 4 + i;
        if (gr < N) {
            float4 v = make_float4(acc[i][0], acc[i][1], acc[i][2], acc[i][3]);
            *reinterpret_cast<float4*>(&g_h1[(size_t)gr * F_MID + col0 + tx * 4]) = v;
        }
    }
}

// ---------------------------------------------------------------------------
// 5. scatter1: a1[dst] += h1[src] * dinv[src]*dinv[dst]   (one warp per edge)
// ---------------------------------------------------------------------------
__global__ void scatter1_kernel(int E) {
    int lane = threadIdx.x & 31;
    int warp = (blockIdx.x * blockDim.x + threadIdx.x) >> 5;
    int nwarps = (gridDim.x * blockDim.x) >> 5;
    for (int e = warp; e < E; e += nwarps) {
        int s = g_src[e];
        int d = g_dst[e];
        float nrm = g_dinv[s] * g_dinv[d];
        float4 v = *reinterpret_cast<const float4*>(&g_h1[(size_t)s * F_MID + lane * 4]);
        v.x *= nrm; v.y *= nrm; v.z *= nrm; v.w *= nrm;
        red_add_v4(&g_a1[(size_t)d * F_MID + lane * 4], v);
    }
}

// ---------------------------------------------------------------------------
// 6. GEMM2: g_h2 = relu(a1 + h1*dinv^2 + b1) @ W2
// ---------------------------------------------------------------------------
__global__ void gemm2_kernel(const float* __restrict__ W,
                             const float* __restrict__ b1, int N) {
    __shared__ float xs[64][64];
    __shared__ float ws[64][64];
    int tid = threadIdx.x;
    int tx = tid & 15;
    int ty = tid >> 4;
    int row0 = blockIdx.x * 64;

    float acc[4][4];
#pragma unroll
    for (int i = 0; i < 4; i++)
#pragma unroll
        for (int j = 0; j < 4; j++) acc[i][j] = 0.f;

    for (int k0 = 0; k0 < F_MID; k0 += 64) {
#pragma unroll
        for (int i = 0; i < 4; i++) {
            int t = tid + i * 256;
            int r = t >> 4;
            int c4 = t & 15;
            float4 v = make_float4(0.f, 0.f, 0.f, 0.f);
            int gr = row0 + r;
            if (gr < N) {
                size_t off = (size_t)gr * F_MID + k0 + c4 * 4;
                float4 a = *reinterpret_cast<const float4*>(&g_a1[off]);
                float4 h = *reinterpret_cast<const float4*>(&g_h1[off]);
                float4 b = *reinterpret_cast<const float4*>(&b1[k0 + c4 * 4]);
                float di = g_dinv[gr];
                float d2 = di * di;
                v.x = fmaxf(a.x + h.x * d2 + b.x, 0.f);
                v.y = fmaxf(a.y + h.y * d2 + b.y, 0.f);
                v.z = fmaxf(a.z + h.z * d2 + b.z, 0.f);
                v.w = fmaxf(a.w + h.w * d2 + b.w, 0.f);
            }
            *reinterpret_cast<float4*>(&xs[r][c4 * 4]) = v;
        }
#pragma unroll
        for (int i = 0; i < 4; i++) {
            int t = tid + i * 256;
            int r = t >> 4;
            int c4 = t & 15;
            float4 v = *reinterpret_cast<const float4*>(&W[(size_t)(k0 + r) * F_OUT + c4 * 4]);
            *reinterpret_cast<float4*>(&ws[r][c4 * 4]) = v;
        }
        __syncthreads();
#pragma unroll 16
        for (int k = 0; k < 64; k++) {
            float4 w = *reinterpret_cast<float4*>(&ws[k][tx * 4]);
            float x0 = xs[ty * 4 + 0][k];
            float x1 = xs[ty * 4 + 1][k];
            float x2 = xs[ty * 4 + 2][k];
            float x3 = xs[ty * 4 + 3][k];
            acc[0][0] += x0 * w.x; acc[0][1] += x0 * w.y; acc[0][2] += x0 * w.z; acc[0][3] += x0 * w.w;
            acc[1][0] += x1 * w.x; acc[1][1] += x1 * w.y; acc[1][2] += x1 * w.z; acc[1][3] += x1 * w.w;
            acc[2][0] += x2 * w.x; acc[2][1] += x2 * w.y; acc[2][2] += x2 * w.z; acc[2][3] += x2 * w.w;
            acc[3][0] += x3 * w.x; acc[3][1] += x3 * w.y; acc[3][2] += x3 * w.z; acc[3][3] += x3 * w.w;
        }
        __syncthreads();
    }
#pragma unroll
    for (int i = 0; i < 4; i++) {
        int gr = row0 + ty * 4 + i;
        if (gr < N) {
            float4 v = make_float4(acc[i][0], acc[i][1], acc[i][2], acc[i][3]);
            *reinterpret_cast<float4*>(&g_h2[(size_t)gr * F_OUT + tx * 4]) = v;
        }
    }
}

// ---------------------------------------------------------------------------
// 7. scatter2: a2[dst] += h2[src]*norm     (two edges per warp, 16 lanes each)
// ---------------------------------------------------------------------------
__global__ void scatter2_kernel(int E) {
    int lane = threadIdx.x & 31;
    int sub = lane >> 4;
    int l = lane & 15;
    int warp = (blockIdx.x * blockDim.x + threadIdx.x) >> 5;
    int nwarps = (gridDim.x * blockDim.x) >> 5;
    int npairs = (E + 1) >> 1;
    for (int p = warp; p < npairs; p += nwarps) {
        int e = 2 * p + sub;
        if (e < E) {
            int s = g_src[e];
            int d = g_dst[e];
            float nrm = g_dinv[s] * g_dinv[d];
            float4 v = *reinterpret_cast<const float4*>(&g_h2[(size_t)s * F_OUT + l * 4]);
            v.x *= nrm; v.y *= nrm; v.z *= nrm; v.w *= nrm;
            red_add_v4(&g_a2[(size_t)d * F_OUT + l * 4], v);
        }
    }
}

// ---------------------------------------------------------------------------
// 8. finalize: v = a2 + h2*dinv^2 + b2 ; out = log_softmax(v)  (warp per row)
// ---------------------------------------------------------------------------
__global__ void finalize_kernel(const float* __restrict__ b2,
                                float* __restrict__ out, int N) {
    int lane = threadIdx.x & 31;
    int warp = (blockIdx.x * blockDim.x + threadIdx.x) >> 5;
    int nwarps = (gridDim.x * blockDim.x) >> 5;
    for (int r = warp; r < N; r += nwarps) {
        float di = g_dinv[r];
        float d2 = di * di;
        size_t base = (size_t)r * F_OUT;
        float v0 = g_a2[base + lane]      + g_h2[base + lane]      * d2 + b2[lane];
        float v1 = g_a2[base + lane + 32] + g_h2[base + lane + 32] * d2 + b2[lane + 32];
        float m = fmaxf(v0, v1);
#pragma unroll
        for (int o = 16; o; o >>= 1) m = fmaxf(m, __shfl_xor_sync(0xffffffffu, m, o));
        float s = __expf(v0 - m) + __expf(v1 - m);
#pragma unroll
        for (int o = 16; o; o >>= 1) s += __shfl_xor_sync(0xffffffffu, s, o);
        float lse = m + __logf(s);
        out[base + lane]      = v0 - lse;
        out[base + lane + 32] = v1 - lse;
    }
}

// ---------------------------------------------------------------------------
extern "C" void kernel_launch(void* const* d_in, const int* in_sizes, int n_in,
                              void* d_out, int out_size) {
    const float* x  = (const float*)d_in[0];
    const void*  ei = d_in[1];
    const float* W1 = (const float*)d_in[2];
    const float* b1 = (const float*)d_in[3];
    const float* W2 = (const float*)d_in[4];
    const float* b2 = (const float*)d_in[5];
    float* out = (float*)d_out;

    int N = in_sizes[0] / F_IN;     // 100000
    int E = in_sizes[1] / 2;        // 1600000
    if (N > NMAX) N = NMAX;
    if (E > EMAX) E = EMAX;

    detect_kernel<<<1, 32>>>((const int*)ei);
    zero_kernel<<<2048, 256>>>();
    edge_prep_kernel<<<2048, 256>>>(ei, E, N);
    dinv_kernel<<<(N + 255) / 256, 256>>>(N);
    gemm1_kernel<<<dim3((N + 63) / 64, F_MID / 64), 256>>>(x, W1, N);
    scatter1_kernel<<<4096, 256>>>(E);
    gemm2_kernel<<<dim3((N + 63) / 64, 1), 256>>>(W2, b1, N);
    scatter2_kernel<<<4096, 256>>>(E);
    finalize_kernel<<<1024, 256>>>(b2, out, N);
}